// round 2
// baseline (speedup 1.0000x reference)
#include <cuda_runtime.h>
#include <math.h>
#include <stddef.h>

// Problem constants
#define TT 256
#define BB 64
#define HH 1024
#define IN3H 3072          // 3*H
#define INK 2048           // input width for every layer (IN = 2H = 2048)

#define REC_BLOCKS 96      // 2 dirs * 48 column tiles (<=148 SMs -> co-resident)
#define REC_THREADS 256

// ---------------------------------------------------------------------------
// Scratch (device globals -- no allocation allowed)
// ---------------------------------------------------------------------------
__device__ float g_gx[2][(size_t)TT * BB * IN3H];    // precomputed input gates per dir
__device__ float g_gh[2][(size_t)BB * IN3H];         // per-step hidden gates per dir
__device__ float g_h [2][(size_t)BB * HH];           // current hidden state per dir
__device__ float g_buf[2][(size_t)TT * BB * 2 * HH]; // layer output ping-pong

// Software grid barrier state (monotonic phase -> replay-safe, no reset races)
__device__ unsigned g_bar_count = 0;
__device__ unsigned g_bar_phase = 0;

// ---------------------------------------------------------------------------
// NT SGEMM:  C[m,n] = sum_k A[m,k] * W[n,k] + bias[n]
// 64x64 tile, BK=16, 256 threads, 4x4 microtile. blockIdx.z = direction.
// ---------------------------------------------------------------------------
struct GemmArgs {
    const float* A[2];
    const float* W[2];
    const float* bias[2];
    float*       C[2];
    int M, N, K;
};

__global__ __launch_bounds__(256) void gemm_nt_kernel(GemmArgs g) {
    const int d = blockIdx.z;
    const float* __restrict__ A    = g.A[d];
    const float* __restrict__ W    = g.W[d];
    const float* __restrict__ bias = g.bias[d];
    float* __restrict__ C          = g.C[d];
    const int K = g.K, N = g.N;

    const int bm = blockIdx.y * 64;
    const int bn = blockIdx.x * 64;

    __shared__ float As[16][68];
    __shared__ float Ws[16][68];

    const int tid = threadIdx.x;
    const int lr  = tid >> 2;
    const int lk  = (tid & 3) << 2;
    const int tx  = tid & 15;
    const int ty  = tid >> 4;

    const float* Aptr = A + (size_t)(bm + lr) * K + lk;
    const float* Wptr = W + (size_t)(bn + lr) * K + lk;

    float acc[4][4];
#pragma unroll
    for (int i = 0; i < 4; i++)
#pragma unroll
        for (int j = 0; j < 4; j++) acc[i][j] = 0.f;

    for (int k0 = 0; k0 < K; k0 += 16) {
        float4 av = *(const float4*)(Aptr + k0);
        float4 wv = *(const float4*)(Wptr + k0);
        As[lk + 0][lr] = av.x; As[lk + 1][lr] = av.y;
        As[lk + 2][lr] = av.z; As[lk + 3][lr] = av.w;
        Ws[lk + 0][lr] = wv.x; Ws[lk + 1][lr] = wv.y;
        Ws[lk + 2][lr] = wv.z; Ws[lk + 3][lr] = wv.w;
        __syncthreads();

#pragma unroll
        for (int kk = 0; kk < 16; kk++) {
            float4 a4 = *(const float4*)&As[kk][ty << 2];
            float4 b4 = *(const float4*)&Ws[kk][tx << 2];
            float avv[4] = {a4.x, a4.y, a4.z, a4.w};
            float bvv[4] = {b4.x, b4.y, b4.z, b4.w};
#pragma unroll
            for (int i = 0; i < 4; i++)
#pragma unroll
                for (int j = 0; j < 4; j++) acc[i][j] += avv[i] * bvv[j];
        }
        __syncthreads();
    }

    const int ncol = bn + (tx << 2);
    float4 bb = *(const float4*)&bias[ncol];
#pragma unroll
    for (int i = 0; i < 4; i++) {
        size_t m = (size_t)(bm + (ty << 2) + i);
        float4 o;
        o.x = acc[i][0] + bb.x;
        o.y = acc[i][1] + bb.y;
        o.z = acc[i][2] + bb.z;
        o.w = acc[i][3] + bb.w;
        *(float4*)&C[m * N + ncol] = o;
    }
}

// ---------------------------------------------------------------------------
// Grid-wide barrier (spin). local_phase tracks monotonic g_bar_phase.
// ---------------------------------------------------------------------------
__device__ __forceinline__ void grid_sync(unsigned& local_phase) {
    __threadfence();
    __syncthreads();
    if (threadIdx.x == 0) {
        unsigned ph = local_phase;
        if (atomicAdd(&g_bar_count, 1u) == REC_BLOCKS - 1) {
            g_bar_count = 0;
            __threadfence();
            atomicAdd(&g_bar_phase, 1u);
        } else {
            while (*(volatile unsigned*)&g_bar_phase == ph) { }
        }
        __threadfence();
    }
    __syncthreads();
    local_phase++;
}

// ---------------------------------------------------------------------------
// Persistent recurrent kernel: one launch runs all 256 timesteps of one layer,
// both directions. 96 blocks: each owns a (dir, 64-col) gh tile per step, then
// the grid cooperatively applies the GRU gate update.
// ---------------------------------------------------------------------------
__global__ __launch_bounds__(REC_THREADS)
void gru_recurrent_kernel(const float* __restrict__ h0_layer,   // [2, B, H]
                          const float* __restrict__ whh_layer,  // [2, 3H, H]
                          const float* __restrict__ bhh_layer,  // [2, 3H]
                          float* __restrict__ outbuf,           // [T, B, 2H]
                          float* __restrict__ hn_out)           // [2, B, H]
{
    const int bid = blockIdx.x;
    const int d   = bid / 48;          // direction for the GEMM phase
    const int bn  = (bid % 48) * 64;   // column tile within [0, 3072)

    const float* __restrict__ W    = whh_layer + (size_t)d * IN3H * HH;
    const float* __restrict__ bias = bhh_layer + (size_t)d * IN3H;
    float* __restrict__ Cgh        = g_gh[d];

    __shared__ float As[16][68];
    __shared__ float Ws[16][68];

    const int tid = threadIdx.x;
    const int lr  = tid >> 2;
    const int lk  = (tid & 3) << 2;
    const int tx  = tid & 15;
    const int ty  = tid >> 4;

    unsigned phase = *(volatile unsigned*)&g_bar_phase;
    __syncthreads();   // all threads read phase before any barrier arrival

    const float* Wbase = W + (size_t)(bn + lr) * HH + lk;
    const int ncol = bn + (tx << 2);
    const float4 bb = *(const float4*)&bias[ncol];

    for (int s = 0; s < TT; s++) {
        // ---- GEMM phase: gh[d][0:64, bn:bn+64] = h @ Whh^T + bhh ----
        const float* Abase = (s == 0) ? (h0_layer + (size_t)d * BB * HH)
                                      : g_h[d];
        const float* Aptr = Abase + (size_t)lr * HH + lk;

        float acc[4][4];
#pragma unroll
        for (int i = 0; i < 4; i++)
#pragma unroll
            for (int j = 0; j < 4; j++) acc[i][j] = 0.f;

        for (int k0 = 0; k0 < HH; k0 += 16) {
            float4 av = *(const float4*)(Aptr + k0);
            float4 wv = *(const float4*)(Wbase + k0);
            As[lk + 0][lr] = av.x; As[lk + 1][lr] = av.y;
            As[lk + 2][lr] = av.z; As[lk + 3][lr] = av.w;
            Ws[lk + 0][lr] = wv.x; Ws[lk + 1][lr] = wv.y;
            Ws[lk + 2][lr] = wv.z; Ws[lk + 3][lr] = wv.w;
            __syncthreads();

#pragma unroll
            for (int kk = 0; kk < 16; kk++) {
                float4 a4 = *(const float4*)&As[kk][ty << 2];
                float4 b4 = *(const float4*)&Ws[kk][tx << 2];
                float avv[4] = {a4.x, a4.y, a4.z, a4.w};
                float bvv[4] = {b4.x, b4.y, b4.z, b4.w};
#pragma unroll
                for (int i = 0; i < 4; i++)
#pragma unroll
                    for (int j = 0; j < 4; j++) acc[i][j] += avv[i] * bvv[j];
            }
            __syncthreads();
        }

#pragma unroll
        for (int i = 0; i < 4; i++) {
            int m = (ty << 2) + i;   // batch row
            float4 o;
            o.x = acc[i][0] + bb.x;
            o.y = acc[i][1] + bb.y;
            o.z = acc[i][2] + bb.z;
            o.w = acc[i][3] + bb.w;
            *(float4*)&Cgh[(size_t)m * IN3H + ncol] = o;
        }

        grid_sync(phase);

        // ---- Gate phase: all 2*B*H elements spread across the grid ----
        for (int i = bid * REC_THREADS + tid; i < 2 * BB * HH;
             i += REC_BLOCKS * REC_THREADS) {
            const int d2  = i >> 16;           // /(B*H)
            const int rem = i & 0xFFFF;
            const int b   = rem >> 10;
            const int j   = rem & 1023;
            const int t   = (d2 == 0) ? s : (TT - 1 - s);

            const float* __restrict__ gxp = &g_gx[d2][((size_t)t * BB + b) * IN3H];
            const float* __restrict__ ghp = &g_gh[d2][(size_t)b * IN3H];

            float r = 1.f / (1.f + expf(-(gxp[j]          + ghp[j])));
            float z = 1.f / (1.f + expf(-(gxp[HH + j]     + ghp[HH + j])));
            float n = tanhf(gxp[2 * HH + j] + r * ghp[2 * HH + j]);

            float hold = (s == 0) ? h0_layer[(size_t)d2 * BB * HH + rem]
                                  : g_h[d2][rem];
            float hnew = n + z * (hold - n);
            g_h[d2][rem] = hnew;

            outbuf[((size_t)t * BB + b) * (2 * HH) + (size_t)d2 * HH + j] = hnew;
            if (s == TT - 1) hn_out[(size_t)d2 * BB * HH + rem] = hnew;
        }

        grid_sync(phase);
    }
}

// ---------------------------------------------------------------------------
// Launch: 6 graph nodes total (3 x [gx GEMM + persistent recurrent])
// ---------------------------------------------------------------------------
extern "C" void kernel_launch(void* const* d_in, const int* in_sizes, int n_in,
                              void* d_out, int out_size) {
    const float* x   = (const float*)d_in[0];  // [T, B, 2048]
    const float* h0  = (const float*)d_in[1];  // [6, B, H]
    const float* wih = (const float*)d_in[2];  // [3, 2, 3072, 2048]
    const float* whh = (const float*)d_in[3];  // [3, 2, 3072, 1024]
    const float* bih = (const float*)d_in[4];  // [3, 2, 3072]
    const float* bhh = (const float*)d_in[5];  // [3, 2, 3072]
    float* out = (float*)d_out;                // [6, B, H]

    float *gx, *buf;
    cudaGetSymbolAddress((void**)&gx,  g_gx);
    cudaGetSymbolAddress((void**)&buf, g_buf);

    const size_t GX_STRIDE  = (size_t)TT * BB * IN3H;
    const size_t BUF_STRIDE = (size_t)TT * BB * 2 * HH;

    const float* layer_in  = x;
    float*       layer_out = buf;

    for (int l = 0; l < 3; l++) {
        // gx = input @ Wih^T + bih  (both directions, one launch)
        GemmArgs ga;
        for (int d = 0; d < 2; d++) {
            ga.A[d]    = layer_in;
            ga.W[d]    = wih + ((size_t)(l * 2 + d)) * IN3H * INK;
            ga.bias[d] = bih + (size_t)(l * 2 + d) * IN3H;
            ga.C[d]    = gx + (size_t)d * GX_STRIDE;
        }
        ga.M = TT * BB; ga.N = IN3H; ga.K = INK;
        gemm_nt_kernel<<<dim3(IN3H / 64, (TT * BB) / 64, 2), 256>>>(ga);

        // one persistent launch runs all 256 recurrent steps for this layer
        gru_recurrent_kernel<<<REC_BLOCKS, REC_THREADS>>>(
            h0  + (size_t)l * 2 * BB * HH,
            whh + (size_t)l * 2 * IN3H * HH,
            bhh + (size_t)l * 2 * IN3H,
            layer_out,
            out + (size_t)l * 2 * BB * HH);

        layer_in  = layer_out;
        layer_out = (layer_out == buf) ? (buf + BUF_STRIDE) : buf;
    }
}

// round 4
// speedup vs baseline: 2.6290x; 2.6290x over previous
#include <cuda_runtime.h>
#include <cuda_bf16.h>
#include <math.h>
#include <stdint.h>
#include <stddef.h>

// Problem constants
#define TT 256
#define BB 64
#define HH 1024
#define IN3H 3072          // 3*H
#define INK 2048           // input width of every layer (IN = 2H)
#define GX_M (TT * BB)     // 16384
#define GXSZ ((size_t)GX_M * IN3H)

#define REC_BLOCKS 96
#define REC_THREADS 256

// ---------------------------------------------------------------------------
// Scratch (device globals -- no allocation allowed)
// ---------------------------------------------------------------------------
__device__ float g_gx[2 * GXSZ];                       // input gates (fp32)
__device__ float g_gh[2][(size_t)BB * IN3H];           // per-step hidden gates
__device__ float g_h [2 * BB * HH];                    // hidden state fp32
__device__ __nv_bfloat16 g_hhi[2 * BB * HH];           // hidden state hi/lo
__device__ __nv_bfloat16 g_hlo[2 * BB * HH];
__device__ __nv_bfloat16 g_ahi[(size_t)GX_M * INK];    // layer input hi/lo
__device__ __nv_bfloat16 g_alo[(size_t)GX_M * INK];
__device__ __nv_bfloat16 g_whi[(size_t)6 * IN3H * INK]; // w_ih hi/lo
__device__ __nv_bfloat16 g_wlo[(size_t)6 * IN3H * INK];
__device__ __nv_bfloat16 g_uhi[(size_t)6 * IN3H * HH];  // w_hh hi/lo
__device__ __nv_bfloat16 g_ulo[(size_t)6 * IN3H * HH];

__device__ unsigned g_bar_count = 0;
__device__ unsigned g_bar_phase = 0;

// ---------------------------------------------------------------------------
// Baseline-PTX helpers (valid on compute_103: ldmatrix / mma.sync / cp.async)
// ---------------------------------------------------------------------------
__device__ __forceinline__ uint32_t smem_u32(const void* p) {
    uint32_t a;
    asm("{ .reg .u64 t; cvta.to.shared.u64 t, %1; cvt.u32.u64 %0, t; }"
        : "=r"(a) : "l"(p));
    return a;
}

__device__ __forceinline__ void cp_async16(uint32_t dst, const void* src) {
    asm volatile("cp.async.cg.shared.global [%0], [%1], 16;"
                 :: "r"(dst), "l"(src) : "memory");
}
#define CP_COMMIT() asm volatile("cp.async.commit_group;" ::: "memory")
#define CP_WAIT0()  asm volatile("cp.async.wait_group 0;" ::: "memory")

__device__ __forceinline__ void ldsm4(uint32_t* r, uint32_t addr) {
    asm volatile("ldmatrix.sync.aligned.m8n8.x4.shared.b16 {%0,%1,%2,%3}, [%4];"
                 : "=r"(r[0]), "=r"(r[1]), "=r"(r[2]), "=r"(r[3]) : "r"(addr));
}

__device__ __forceinline__ void mma_bf16(float* c, const uint32_t* a,
                                         uint32_t b0, uint32_t b1) {
    asm volatile(
        "mma.sync.aligned.m16n8k16.row.col.f32.bf16.bf16.f32 "
        "{%0,%1,%2,%3}, {%4,%5,%6,%7}, {%8,%9}, {%0,%1,%2,%3};"
        : "+f"(c[0]), "+f"(c[1]), "+f"(c[2]), "+f"(c[3])
        : "r"(a[0]), "r"(a[1]), "r"(a[2]), "r"(a[3]), "r"(b0), "r"(b1));
}

// ---------------------------------------------------------------------------
// Split fp32 -> (bf16 hi, bf16 lo)
// ---------------------------------------------------------------------------
__device__ __forceinline__ uint32_t pack2bf(float a, float b) {
    __nv_bfloat162 t = __floats2bfloat162_rn(a, b);
    return *(uint32_t*)&t;
}

__global__ __launch_bounds__(256) void split_bf16_kernel(
    const float* __restrict__ src, __nv_bfloat16* __restrict__ hi,
    __nv_bfloat16* __restrict__ lo, size_t n4) {
    size_t i = (size_t)blockIdx.x * 256 + threadIdx.x;
    if (i >= n4) return;
    float4 v = ((const float4*)src)[i];
    float h0 = __bfloat162float(__float2bfloat16(v.x));
    float h1 = __bfloat162float(__float2bfloat16(v.y));
    float h2 = __bfloat162float(__float2bfloat16(v.z));
    float h3 = __bfloat162float(__float2bfloat16(v.w));
    uint2 hv, lv;
    hv.x = pack2bf(v.x, v.y);           hv.y = pack2bf(v.z, v.w);
    lv.x = pack2bf(v.x - h0, v.y - h1); lv.y = pack2bf(v.z - h2, v.w - h3);
    ((uint2*)hi)[i] = hv;
    ((uint2*)lo)[i] = lv;
}

// ---------------------------------------------------------------------------
// gx GEMM: C[m,n] = sum_k (Ahi+Alo)[m,k]*(Whi+Wlo)[n,k] + bias[n]
// (lo*lo dropped). 128x128 block tile, k-chunk 32, cp.async double buffer.
// smem matrix layout: [128 rows][40 bf16] (80B row stride; 16B aligned).
// stage: Ahi @0, Alo @10240, Bhi @20480, Blo @30720.
// ---------------------------------------------------------------------------
#define GX_STAGE 40960
#define GX_SMEM  (2 * GX_STAGE)

__device__ __forceinline__ void gx_load(uint32_t sm, int bm, int bn, int k0,
                                        int tid, const __nv_bfloat16* Bhi,
                                        const __nv_bfloat16* Blo) {
#pragma unroll
    for (int half = 0; half < 2; half++) {
        int idx = half * 256 + tid;      // 0..511
        int r   = idx >> 2;
        int co  = k0 + (idx & 3) * 8;
        uint32_t dst = sm + r * 80 + (idx & 3) * 16;
        cp_async16(dst,          g_ahi + (size_t)(bm + r) * INK + co);
        cp_async16(dst + 10240,  g_alo + (size_t)(bm + r) * INK + co);
        cp_async16(dst + 20480,  Bhi   + (size_t)(bn + r) * INK + co);
        cp_async16(dst + 30720,  Blo   + (size_t)(bn + r) * INK + co);
    }
}

__global__ __launch_bounds__(256) void gx_mma_kernel(
    const __nv_bfloat16* __restrict__ Whi,   // [2][3072][2048] (this layer)
    const __nv_bfloat16* __restrict__ Wlo,
    const float* __restrict__ bias)          // [2][3072]
{
    extern __shared__ char smem[];
    const uint32_t sb = smem_u32(smem);
    const int tid = threadIdx.x, wid = tid >> 5, lid = tid & 31;
    const int bn = blockIdx.x * 128;
    const int bm = blockIdx.y * 128;
    const int d  = blockIdx.z;

    const __nv_bfloat16* Bhi = Whi + (size_t)d * IN3H * INK;
    const __nv_bfloat16* Blo = Wlo + (size_t)d * IN3H * INK;
    const float* bptr = bias + d * IN3H;
    float* C = g_gx + (size_t)d * GXSZ;

    // ldmatrix per-thread offsets (A: x4 of 16x16; B: x4 covering n16 x k16)
    const uint32_t aoff = (uint32_t)(((wid & 3) * 32 + (lid & 7) + ((lid >> 3) & 1) * 8) * 80
                                     + ((lid >> 4) & 1) * 16);
    const uint32_t boff = (uint32_t)(((wid >> 2) * 64 + (lid & 7) + ((lid >> 4) & 1) * 8) * 80
                                     + ((lid >> 3) & 1) * 16);

    float acc[2][8][4];
#pragma unroll
    for (int i = 0; i < 2; i++)
#pragma unroll
        for (int j = 0; j < 8; j++)
#pragma unroll
            for (int q = 0; q < 4; q++) acc[i][j][q] = 0.f;

    gx_load(sb, bm, bn, 0, tid, Bhi, Blo);
    CP_COMMIT();

    for (int c = 0; c < 64; c++) {
        CP_WAIT0();
        __syncthreads();
        if (c < 63) {
            gx_load(sb + ((c + 1) & 1) * GX_STAGE, bm, bn, (c + 1) * 32, tid, Bhi, Blo);
            CP_COMMIT();
        }
        const uint32_t st = sb + (c & 1) * GX_STAGE;

#pragma unroll
        for (int kk = 0; kk < 2; kk++) {
            const uint32_t ko = kk * 32;   // 16 bf16 = 32 bytes
            uint32_t ah[2][4], al[2][4];
            ldsm4(ah[0], st + aoff + ko);
            ldsm4(ah[1], st + aoff + 1280 + ko);
            ldsm4(al[0], st + 10240 + aoff + ko);
            ldsm4(al[1], st + 10240 + aoff + 1280 + ko);
#pragma unroll
            for (int g = 0; g < 4; g++) {
                uint32_t bh[4], bl[4];
                ldsm4(bh, st + 20480 + boff + g * 1280 + ko);
                ldsm4(bl, st + 30720 + boff + g * 1280 + ko);
#pragma unroll
                for (int mt = 0; mt < 2; mt++) {
                    mma_bf16(acc[mt][2 * g],     ah[mt], bh[0], bh[1]);
                    mma_bf16(acc[mt][2 * g + 1], ah[mt], bh[2], bh[3]);
                    mma_bf16(acc[mt][2 * g],     ah[mt], bl[0], bl[1]);
                    mma_bf16(acc[mt][2 * g + 1], ah[mt], bl[2], bl[3]);
                    mma_bf16(acc[mt][2 * g],     al[mt], bh[0], bh[1]);
                    mma_bf16(acc[mt][2 * g + 1], al[mt], bh[2], bh[3]);
                }
            }
        }
        __syncthreads();
    }

    // Epilogue: D + bias -> fp32 gx
    const int lr = lid >> 2;
    const int lc = (lid & 3) * 2;
#pragma unroll
    for (int mt = 0; mt < 2; mt++) {
        const int row = bm + (wid & 3) * 32 + mt * 16 + lr;
#pragma unroll
        for (int nt = 0; nt < 8; nt++) {
            const int col = bn + (wid >> 2) * 64 + nt * 8 + lc;
            float b0 = bptr[col], b1 = bptr[col + 1];
            float* c = acc[mt][nt];
            C[(size_t)row * IN3H + col]           = c[0] + b0;
            C[(size_t)row * IN3H + col + 1]       = c[1] + b1;
            C[(size_t)(row + 8) * IN3H + col]     = c[2] + b0;
            C[(size_t)(row + 8) * IN3H + col + 1] = c[3] + b1;
        }
    }
}

// ---------------------------------------------------------------------------
// Grid-wide barrier (spin, monotonic phase) -- proven in R2
// ---------------------------------------------------------------------------
__device__ __forceinline__ void grid_sync(unsigned& local_phase) {
    __threadfence();
    __syncthreads();
    if (threadIdx.x == 0) {
        unsigned ph = local_phase;
        if (atomicAdd(&g_bar_count, 1u) == REC_BLOCKS - 1) {
            g_bar_count = 0;
            __threadfence();
            atomicAdd(&g_bar_phase, 1u);
        } else {
            while (*(volatile unsigned*)&g_bar_phase == ph) { }
        }
        __threadfence();
    }
    __syncthreads();
    local_phase++;
}

// ---------------------------------------------------------------------------
// Persistent recurrent kernel: 96 blocks, 256 steps. Per step each block does
// a 64x64x1024 3-product bf16 mma GEMM for its gh column tile, then the grid
// applies the GRU gate update (emitting fp32 h + bf16 hi/lo for next step and
// next layer).
// smem: [2 stages][ Hhi@0 | Hlo@5120 | Whi@10240 | Wlo@15360 ], 64x40 bf16 each
// ---------------------------------------------------------------------------
#define REC_STAGE 20480

__device__ __forceinline__ void rec_load(uint32_t sm, const __nv_bfloat16* hhi,
                                         const __nv_bfloat16* hlo,
                                         const __nv_bfloat16* Whi,
                                         const __nv_bfloat16* Wlo,
                                         int bn, int k0, int tid) {
    int r  = tid >> 2;
    int co = k0 + (tid & 3) * 8;
    uint32_t dst = sm + r * 80 + (tid & 3) * 16;
    cp_async16(dst,          hhi + (size_t)r * HH + co);
    cp_async16(dst + 5120,   hlo + (size_t)r * HH + co);
    cp_async16(dst + 10240,  Whi + (size_t)(bn + r) * HH + co);
    cp_async16(dst + 15360,  Wlo + (size_t)(bn + r) * HH + co);
}

__global__ __launch_bounds__(REC_THREADS)
void gru_recurrent_kernel(const float* __restrict__ h0_layer,    // [2,B,H]
                          const __nv_bfloat16* __restrict__ Uhi, // [2,3H,H]
                          const __nv_bfloat16* __restrict__ Ulo,
                          const float* __restrict__ bhh_layer,   // [2,3H]
                          float* __restrict__ hn_out)            // [2,B,H]
{
    __shared__ __align__(16) char rs[2 * REC_STAGE];
    const uint32_t sb = smem_u32(rs);
    const int bid = blockIdx.x, tid = threadIdx.x;
    const int wid = tid >> 5, lid = tid & 31;
    const int d  = bid / 48;
    const int bn = (bid % 48) * 64;

    const __nv_bfloat16* Whi = Uhi + (size_t)d * IN3H * HH;
    const __nv_bfloat16* Wlo = Ulo + (size_t)d * IN3H * HH;
    const float* bias = bhh_layer + d * IN3H;
    float* Cgh = g_gh[d];

    unsigned phase = *(volatile unsigned*)&g_bar_phase;
    __syncthreads();

    // Prologue: split h0 into fp32 + bf16 hi/lo state
    for (int i = bid * REC_THREADS + tid; i < 2 * BB * HH;
         i += REC_BLOCKS * REC_THREADS) {
        float v = h0_layer[i];
        g_h[i] = v;
        __nv_bfloat16 hi = __float2bfloat16(v);
        g_hhi[i] = hi;
        g_hlo[i] = __float2bfloat16(v - __bfloat162float(hi));
    }
    grid_sync(phase);

    const uint32_t aoff = (uint32_t)(((wid & 1) * 32 + (lid & 7) + ((lid >> 3) & 1) * 8) * 80
                                     + ((lid >> 4) & 1) * 16);
    const uint32_t boff = (uint32_t)(((wid >> 1) * 16 + (lid & 7) + ((lid >> 4) & 1) * 8) * 80
                                     + ((lid >> 3) & 1) * 16);
    const __nv_bfloat16* hhi = g_hhi + (size_t)d * BB * HH;
    const __nv_bfloat16* hlo = g_hlo + (size_t)d * BB * HH;

    for (int s = 0; s < TT; s++) {
        float acc[2][2][4];
#pragma unroll
        for (int i = 0; i < 2; i++)
#pragma unroll
            for (int j = 0; j < 2; j++)
#pragma unroll
                for (int q = 0; q < 4; q++) acc[i][j][q] = 0.f;

        rec_load(sb, hhi, hlo, Whi, Wlo, bn, 0, tid);
        CP_COMMIT();

        for (int c = 0; c < 32; c++) {
            CP_WAIT0();
            __syncthreads();
            if (c < 31) {
                rec_load(sb + ((c + 1) & 1) * REC_STAGE, hhi, hlo, Whi, Wlo,
                         bn, (c + 1) * 32, tid);
                CP_COMMIT();
            }
            const uint32_t st = sb + (c & 1) * REC_STAGE;

#pragma unroll
            for (int kk = 0; kk < 2; kk++) {
                const uint32_t ko = kk * 32;
                uint32_t ah[2][4], al[2][4], bh[4], bl[4];
                ldsm4(ah[0], st + aoff + ko);
                ldsm4(ah[1], st + aoff + 1280 + ko);
                ldsm4(al[0], st + 5120 + aoff + ko);
                ldsm4(al[1], st + 5120 + aoff + 1280 + ko);
                ldsm4(bh,    st + 10240 + boff + ko);
                ldsm4(bl,    st + 15360 + boff + ko);
#pragma unroll
                for (int mt = 0; mt < 2; mt++) {
                    mma_bf16(acc[mt][0], ah[mt], bh[0], bh[1]);
                    mma_bf16(acc[mt][1], ah[mt], bh[2], bh[3]);
                    mma_bf16(acc[mt][0], ah[mt], bl[0], bl[1]);
                    mma_bf16(acc[mt][1], ah[mt], bl[2], bl[3]);
                    mma_bf16(acc[mt][0], al[mt], bh[0], bh[1]);
                    mma_bf16(acc[mt][1], al[mt], bh[2], bh[3]);
                }
            }
            __syncthreads();
        }

        // Epilogue: gh tile + bias
        {
            const int lr = lid >> 2;
            const int lc = (lid & 3) * 2;
#pragma unroll
            for (int mt = 0; mt < 2; mt++) {
                const int row = (wid & 1) * 32 + mt * 16 + lr;
#pragma unroll
                for (int nt = 0; nt < 2; nt++) {
                    const int col = bn + (wid >> 1) * 16 + nt * 8 + lc;
                    float b0 = bias[col], b1 = bias[col + 1];
                    float* c = acc[mt][nt];
                    Cgh[(size_t)row * IN3H + col]           = c[0] + b0;
                    Cgh[(size_t)row * IN3H + col + 1]       = c[1] + b1;
                    Cgh[(size_t)(row + 8) * IN3H + col]     = c[2] + b0;
                    Cgh[(size_t)(row + 8) * IN3H + col + 1] = c[3] + b1;
                }
            }
        }

        grid_sync(phase);

        // Gate phase
        for (int i = bid * REC_THREADS + tid; i < 2 * BB * HH;
             i += REC_BLOCKS * REC_THREADS) {
            const int d2  = i >> 16;
            const int rem = i & 0xFFFF;
            const int b   = rem >> 10;
            const int j   = rem & 1023;
            const int t   = d2 ? (TT - 1 - s) : s;

            const float* gxp = g_gx + (size_t)d2 * GXSZ + ((size_t)t * BB + b) * IN3H;
            const float* ghp = g_gh[d2] + (size_t)b * IN3H;

            float r = 1.f / (1.f + expf(-(gxp[j]      + ghp[j])));
            float z = 1.f / (1.f + expf(-(gxp[HH + j] + ghp[HH + j])));
            float n = tanhf(gxp[2 * HH + j] + r * ghp[2 * HH + j]);

            float hold = g_h[i];
            float hnew = n + z * (hold - n);
            g_h[i] = hnew;

            __nv_bfloat16 hi = __float2bfloat16(hnew);
            __nv_bfloat16 lo = __float2bfloat16(hnew - __bfloat162float(hi));
            g_hhi[i] = hi;
            g_hlo[i] = lo;

            size_t oidx = ((size_t)t * BB + b) * INK + (size_t)d2 * HH + j;
            g_ahi[oidx] = hi;
            g_alo[oidx] = lo;

            if (s == TT - 1) hn_out[i] = hnew;
        }

        grid_sync(phase);
    }
}

// ---------------------------------------------------------------------------
// Launch: 3 split preps + 3 x [gx mma GEMM + persistent GRU] = 9 graph nodes
// ---------------------------------------------------------------------------
extern "C" void kernel_launch(void* const* d_in, const int* in_sizes, int n_in,
                              void* d_out, int out_size) {
    const float* x   = (const float*)d_in[0];  // [T, B, 2048]
    const float* h0  = (const float*)d_in[1];  // [6, B, H]
    const float* wih = (const float*)d_in[2];  // [3, 2, 3072, 2048]
    const float* whh = (const float*)d_in[3];  // [3, 2, 3072, 1024]
    const float* bih = (const float*)d_in[4];  // [3, 2, 3072]
    const float* bhh = (const float*)d_in[5];  // [3, 2, 3072]
    float* out = (float*)d_out;                // [6, B, H]

    __nv_bfloat16 *ahi, *alo, *whi, *wlo, *uhi, *ulo;
    cudaGetSymbolAddress((void**)&ahi, g_ahi);
    cudaGetSymbolAddress((void**)&alo, g_alo);
    cudaGetSymbolAddress((void**)&whi, g_whi);
    cudaGetSymbolAddress((void**)&wlo, g_wlo);
    cudaGetSymbolAddress((void**)&uhi, g_uhi);
    cudaGetSymbolAddress((void**)&ulo, g_ulo);

    cudaFuncSetAttribute(gx_mma_kernel,
                         cudaFuncAttributeMaxDynamicSharedMemorySize, GX_SMEM);

    {   // split w_ih
        size_t n4 = (size_t)6 * IN3H * INK / 4;
        split_bf16_kernel<<<(unsigned)((n4 + 255) / 256), 256>>>(wih, whi, wlo, n4);
    }
    {   // split w_hh
        size_t n4 = (size_t)6 * IN3H * HH / 4;
        split_bf16_kernel<<<(unsigned)((n4 + 255) / 256), 256>>>(whh, uhi, ulo, n4);
    }
    {   // split x (layer-0 input)
        size_t n4 = (size_t)GX_M * INK / 4;
        split_bf16_kernel<<<(unsigned)((n4 + 255) / 256), 256>>>(x, ahi, alo, n4);
    }

    for (int l = 0; l < 3; l++) {
        gx_mma_kernel<<<dim3(IN3H / 128, GX_M / 128, 2), 256, GX_SMEM>>>(
            whi + (size_t)l * 2 * IN3H * INK,
            wlo + (size_t)l * 2 * IN3H * INK,
            bih + (size_t)l * 2 * IN3H);

        gru_recurrent_kernel<<<REC_BLOCKS, REC_THREADS>>>(
            h0  + (size_t)l * 2 * BB * HH,
            uhi + (size_t)l * 2 * IN3H * HH,
            ulo + (size_t)l * 2 * IN3H * HH,
            bhh + (size_t)l * 2 * IN3H,
            out + (size_t)l * 2 * BB * HH);
    }
}

// round 5
// speedup vs baseline: 3.0232x; 1.1499x over previous
#include <cuda_runtime.h>
#include <cuda_bf16.h>
#include <math.h>
#include <stdint.h>
#include <stddef.h>

// Problem constants
#define TT 256
#define BB 64
#define HH 1024
#define IN3H 3072          // 3*H
#define INK 2048           // input width of every layer (IN = 2H)
#define GX_M (TT * BB)     // 16384
#define GXSZ ((size_t)GX_M * IN3H)

#define REC_BLOCKS 144     // 2 dirs * 24 N-tiles(128) * 3 K-splits
#define REC_THREADS 256

// ---------------------------------------------------------------------------
// Scratch (device globals -- no allocation allowed)
// ---------------------------------------------------------------------------
__device__ float g_gx[2 * GXSZ];                        // input gates (fp32)
__device__ float g_ghp[3][2][(size_t)BB * IN3H];        // hidden-gate partials
__device__ float g_h [2 * BB * HH];                     // hidden state fp32
__device__ __nv_bfloat16 g_hhi[2 * BB * HH];            // hidden state hi/lo
__device__ __nv_bfloat16 g_hlo[2 * BB * HH];
__device__ __nv_bfloat16 g_ahi[(size_t)GX_M * INK];     // layer input hi/lo
__device__ __nv_bfloat16 g_alo[(size_t)GX_M * INK];
__device__ __nv_bfloat16 g_whi[(size_t)6 * IN3H * INK]; // w_ih hi/lo
__device__ __nv_bfloat16 g_wlo[(size_t)6 * IN3H * INK];
__device__ __nv_bfloat16 g_uhi[(size_t)6 * IN3H * HH];  // w_hh hi/lo
__device__ __nv_bfloat16 g_ulo[(size_t)6 * IN3H * HH];

__device__ unsigned g_bar_count = 0;
__device__ unsigned g_bar_phase = 0;

// ---------------------------------------------------------------------------
// Baseline-PTX helpers (valid on compute_103)
// ---------------------------------------------------------------------------
__device__ __forceinline__ uint32_t smem_u32(const void* p) {
    uint32_t a;
    asm("{ .reg .u64 t; cvta.to.shared.u64 t, %1; cvt.u32.u64 %0, t; }"
        : "=r"(a) : "l"(p));
    return a;
}

__device__ __forceinline__ void cp_async16(uint32_t dst, const void* src) {
    asm volatile("cp.async.cg.shared.global [%0], [%1], 16;"
                 :: "r"(dst), "l"(src) : "memory");
}
#define CP_COMMIT() asm volatile("cp.async.commit_group;" ::: "memory")
#define CP_WAIT0()  asm volatile("cp.async.wait_group 0;" ::: "memory")
#define CP_WAIT1()  asm volatile("cp.async.wait_group 1;" ::: "memory")

__device__ __forceinline__ void ldsm4(uint32_t* r, uint32_t addr) {
    asm volatile("ldmatrix.sync.aligned.m8n8.x4.shared.b16 {%0,%1,%2,%3}, [%4];"
                 : "=r"(r[0]), "=r"(r[1]), "=r"(r[2]), "=r"(r[3]) : "r"(addr));
}

// NOTE: not volatile -- lets ptxas schedule around HMMA latency.
__device__ __forceinline__ void mma_bf16(float* c, const uint32_t* a,
                                         uint32_t b0, uint32_t b1) {
    asm("mma.sync.aligned.m16n8k16.row.col.f32.bf16.bf16.f32 "
        "{%0,%1,%2,%3}, {%4,%5,%6,%7}, {%8,%9}, {%0,%1,%2,%3};"
        : "+f"(c[0]), "+f"(c[1]), "+f"(c[2]), "+f"(c[3])
        : "r"(a[0]), "r"(a[1]), "r"(a[2]), "r"(a[3]), "r"(b0), "r"(b1));
}

// ---------------------------------------------------------------------------
// Split fp32 -> (bf16 hi, bf16 lo)
// ---------------------------------------------------------------------------
__device__ __forceinline__ uint32_t pack2bf(float a, float b) {
    __nv_bfloat162 t = __floats2bfloat162_rn(a, b);
    return *(uint32_t*)&t;
}

__global__ __launch_bounds__(256) void split_bf16_kernel(
    const float* __restrict__ src, __nv_bfloat16* __restrict__ hi,
    __nv_bfloat16* __restrict__ lo, size_t n4) {
    size_t i = (size_t)blockIdx.x * 256 + threadIdx.x;
    if (i >= n4) return;
    float4 v = ((const float4*)src)[i];
    float h0 = __bfloat162float(__float2bfloat16(v.x));
    float h1 = __bfloat162float(__float2bfloat16(v.y));
    float h2 = __bfloat162float(__float2bfloat16(v.z));
    float h3 = __bfloat162float(__float2bfloat16(v.w));
    uint2 hv, lv;
    hv.x = pack2bf(v.x, v.y);           hv.y = pack2bf(v.z, v.w);
    lv.x = pack2bf(v.x - h0, v.y - h1); lv.y = pack2bf(v.z - h2, v.w - h3);
    ((uint2*)hi)[i] = hv;
    ((uint2*)lo)[i] = lv;
}

// ---------------------------------------------------------------------------
// gx GEMM: 128x128 tile, k-chunk 32, 3-stage cp.async pipeline.
// smem stage: Ahi@0, Alo@10240, Bhi@20480, Blo@30720 (rows of 80B).
// ---------------------------------------------------------------------------
#define GX_STAGE 40960
#define GX_SMEM  (3 * GX_STAGE)
#define GX_NCHUNK 64

__device__ __forceinline__ void gx_load(uint32_t sm, int bm, int bn, int k0,
                                        int tid, const __nv_bfloat16* Bhi,
                                        const __nv_bfloat16* Blo) {
#pragma unroll
    for (int half = 0; half < 2; half++) {
        int idx = half * 256 + tid;      // 0..511
        int r   = idx >> 2;
        int co  = k0 + (idx & 3) * 8;
        uint32_t dst = sm + r * 80 + (idx & 3) * 16;
        cp_async16(dst,          g_ahi + (size_t)(bm + r) * INK + co);
        cp_async16(dst + 10240,  g_alo + (size_t)(bm + r) * INK + co);
        cp_async16(dst + 20480,  Bhi   + (size_t)(bn + r) * INK + co);
        cp_async16(dst + 30720,  Blo   + (size_t)(bn + r) * INK + co);
    }
}

__global__ __launch_bounds__(256) void gx_mma_kernel(
    const __nv_bfloat16* __restrict__ Whi,   // [2][3072][2048] (this layer)
    const __nv_bfloat16* __restrict__ Wlo,
    const float* __restrict__ bias)          // [2][3072]
{
    extern __shared__ char smem[];
    const uint32_t sb = smem_u32(smem);
    const int tid = threadIdx.x, wid = tid >> 5, lid = tid & 31;
    const int bn = blockIdx.x * 128;
    const int bm = blockIdx.y * 128;
    const int d  = blockIdx.z;

    const __nv_bfloat16* Bhi = Whi + (size_t)d * IN3H * INK;
    const __nv_bfloat16* Blo = Wlo + (size_t)d * IN3H * INK;
    const float* bptr = bias + d * IN3H;
    float* C = g_gx + (size_t)d * GXSZ;

    const uint32_t aoff = (uint32_t)(((wid & 3) * 32 + (lid & 7) + ((lid >> 3) & 1) * 8) * 80
                                     + ((lid >> 4) & 1) * 16);
    const uint32_t boff = (uint32_t)(((wid >> 2) * 64 + (lid & 7) + ((lid >> 4) & 1) * 8) * 80
                                     + ((lid >> 3) & 1) * 16);

    float acc[2][8][4];
#pragma unroll
    for (int i = 0; i < 2; i++)
#pragma unroll
        for (int j = 0; j < 8; j++)
#pragma unroll
            for (int q = 0; q < 4; q++) acc[i][j][q] = 0.f;

    gx_load(sb,            bm, bn,  0, tid, Bhi, Blo); CP_COMMIT();
    gx_load(sb + GX_STAGE, bm, bn, 32, tid, Bhi, Blo); CP_COMMIT();

    for (int c = 0; c < GX_NCHUNK; c++) {
        if (c + 1 < GX_NCHUNK) { CP_WAIT1(); } else { CP_WAIT0(); }
        __syncthreads();
        if (c + 2 < GX_NCHUNK) {
            gx_load(sb + ((c + 2) % 3) * GX_STAGE, bm, bn, (c + 2) * 32, tid, Bhi, Blo);
            CP_COMMIT();
        }
        const uint32_t st = sb + (c % 3) * GX_STAGE;

#pragma unroll
        for (int kk = 0; kk < 2; kk++) {
            const uint32_t ko = kk * 32;
            uint32_t ah[2][4], al[2][4];
            ldsm4(ah[0], st + aoff + ko);
            ldsm4(ah[1], st + aoff + 1280 + ko);
            ldsm4(al[0], st + 10240 + aoff + ko);
            ldsm4(al[1], st + 10240 + aoff + 1280 + ko);
#pragma unroll
            for (int g = 0; g < 4; g++) {
                uint32_t bh[4], bl[4];
                ldsm4(bh, st + 20480 + boff + g * 1280 + ko);
                ldsm4(bl, st + 30720 + boff + g * 1280 + ko);
                // product-major: same-acc reuse distance = 4
                mma_bf16(acc[0][2 * g],     ah[0], bh[0], bh[1]);
                mma_bf16(acc[0][2 * g + 1], ah[0], bh[2], bh[3]);
                mma_bf16(acc[1][2 * g],     ah[1], bh[0], bh[1]);
                mma_bf16(acc[1][2 * g + 1], ah[1], bh[2], bh[3]);
                mma_bf16(acc[0][2 * g],     ah[0], bl[0], bl[1]);
                mma_bf16(acc[0][2 * g + 1], ah[0], bl[2], bl[3]);
                mma_bf16(acc[1][2 * g],     ah[1], bl[0], bl[1]);
                mma_bf16(acc[1][2 * g + 1], ah[1], bl[2], bl[3]);
                mma_bf16(acc[0][2 * g],     al[0], bh[0], bh[1]);
                mma_bf16(acc[0][2 * g + 1], al[0], bh[2], bh[3]);
                mma_bf16(acc[1][2 * g],     al[1], bh[0], bh[1]);
                mma_bf16(acc[1][2 * g + 1], al[1], bh[2], bh[3]);
            }
        }
        __syncthreads();
    }

    // Epilogue: D + bias -> fp32 gx
    const int lr = lid >> 2;
    const int lc = (lid & 3) * 2;
#pragma unroll
    for (int mt = 0; mt < 2; mt++) {
        const int row = bm + (wid & 3) * 32 + mt * 16 + lr;
#pragma unroll
        for (int nt = 0; nt < 8; nt++) {
            const int col = bn + (wid >> 2) * 64 + nt * 8 + lc;
            float b0 = bptr[col], b1 = bptr[col + 1];
            float* c = acc[mt][nt];
            C[(size_t)row * IN3H + col]           = c[0] + b0;
            C[(size_t)row * IN3H + col + 1]       = c[1] + b1;
            C[(size_t)(row + 8) * IN3H + col]     = c[2] + b0;
            C[(size_t)(row + 8) * IN3H + col + 1] = c[3] + b1;
        }
    }
}

// ---------------------------------------------------------------------------
// Grid-wide barrier (spin, monotonic phase)
// ---------------------------------------------------------------------------
__device__ __forceinline__ void grid_sync(unsigned& local_phase) {
    __threadfence();
    __syncthreads();
    if (threadIdx.x == 0) {
        unsigned ph = local_phase;
        if (atomicAdd(&g_bar_count, 1u) == REC_BLOCKS - 1) {
            g_bar_count = 0;
            __threadfence();
            atomicAdd(&g_bar_phase, 1u);
        } else {
            while (*(volatile unsigned*)&g_bar_phase == ph) { }
        }
        __threadfence();
    }
    __syncthreads();
    local_phase++;
}

// ---------------------------------------------------------------------------
// Persistent recurrent kernel: 144 blocks = (dir, 24 N-tiles of 128, 3 K-splits).
// Per step each block computes a 64x128 partial of gh over its K range; gate
// phase sums partials + bias and applies the GRU update.
// smem stage: Ahi@0(5120) Alo@5120 Bhi@10240(10240) Blo@20480 -> 30720B, x3.
// ---------------------------------------------------------------------------
#define RC_STAGE 30720
#define RC_SMEM  (3 * RC_STAGE)

__device__ __forceinline__ void rec_load(uint32_t sm, const __nv_bfloat16* hhi,
                                         const __nv_bfloat16* hlo,
                                         const __nv_bfloat16* Whi,
                                         const __nv_bfloat16* Wlo,
                                         int bn0, int k0, int tid) {
    {   // A: 64 rows x 32k, hi+lo
        int r  = tid >> 2;
        int co = k0 + (tid & 3) * 8;
        uint32_t dst = sm + r * 80 + (tid & 3) * 16;
        cp_async16(dst,        hhi + (size_t)r * HH + co);
        cp_async16(dst + 5120, hlo + (size_t)r * HH + co);
    }
#pragma unroll
    for (int half = 0; half < 2; half++) {  // B: 128 rows x 32k, hi+lo
        int idx = half * 256 + tid;
        int r   = idx >> 2;
        int co  = k0 + (idx & 3) * 8;
        uint32_t dst = sm + 10240 + r * 80 + (idx & 3) * 16;
        cp_async16(dst,         Whi + (size_t)(bn0 + r) * HH + co);
        cp_async16(dst + 10240, Wlo + (size_t)(bn0 + r) * HH + co);
    }
}

__global__ __launch_bounds__(REC_THREADS)
void gru_recurrent_kernel(const float* __restrict__ h0_layer,    // [2,B,H]
                          const __nv_bfloat16* __restrict__ Uhi, // [2,3H,H]
                          const __nv_bfloat16* __restrict__ Ulo,
                          const float* __restrict__ bhh_layer,   // [2,3H]
                          float* __restrict__ hn_out)            // [2,B,H]
{
    extern __shared__ char smem[];
    const uint32_t sb = smem_u32(smem);
    const int bid = blockIdx.x, tid = threadIdx.x;
    const int wid = tid >> 5, lid = tid & 31;
    const int d   = bid / 72;
    const int rem = bid % 72;
    const int nt  = rem / 3;            // 0..23 -> 128 gh columns each
    const int ks  = rem % 3;            // K split
    const int bn0  = nt * 128;
    const int kbeg = (ks == 0) ? 0 : 384 + (ks - 1) * 320;
    const int nc   = (ks == 0) ? 12 : 10;   // chunks of 32

    const __nv_bfloat16* Whi = Uhi + (size_t)d * IN3H * HH;
    const __nv_bfloat16* Wlo = Ulo + (size_t)d * IN3H * HH;
    float* Pout = g_ghp[ks][d];

    unsigned phase = *(volatile unsigned*)&g_bar_phase;
    __syncthreads();

    // Prologue: split h0 into fp32 + bf16 hi/lo state
    for (int i = bid * REC_THREADS + tid; i < 2 * BB * HH;
         i += REC_BLOCKS * REC_THREADS) {
        float v = h0_layer[i];
        g_h[i] = v;
        __nv_bfloat16 hi = __float2bfloat16(v);
        g_hhi[i] = hi;
        g_hlo[i] = __float2bfloat16(v - __bfloat162float(hi));
    }
    grid_sync(phase);

    // warp tile: 32 m-rows (wid&1) x 32 n-cols (wid>>1)
    const uint32_t aoff = (uint32_t)(((wid & 1) * 32 + (lid & 7) + ((lid >> 3) & 1) * 8) * 80
                                     + ((lid >> 4) & 1) * 16);
    const uint32_t boff = (uint32_t)(10240 + ((wid >> 1) * 32 + (lid & 7) + ((lid >> 4) & 1) * 8) * 80
                                     + ((lid >> 3) & 1) * 16);
    const __nv_bfloat16* hhi = g_hhi + (size_t)d * BB * HH;
    const __nv_bfloat16* hlo = g_hlo + (size_t)d * BB * HH;

    for (int s = 0; s < TT; s++) {
        float acc[2][4][4];
#pragma unroll
        for (int i = 0; i < 2; i++)
#pragma unroll
            for (int j = 0; j < 4; j++)
#pragma unroll
                for (int q = 0; q < 4; q++) acc[i][j][q] = 0.f;

        rec_load(sb,            hhi, hlo, Whi, Wlo, bn0, kbeg,      tid); CP_COMMIT();
        rec_load(sb + RC_STAGE, hhi, hlo, Whi, Wlo, bn0, kbeg + 32, tid); CP_COMMIT();

        for (int c = 0; c < nc; c++) {
            if (c + 1 < nc) { CP_WAIT1(); } else { CP_WAIT0(); }
            __syncthreads();
            if (c + 2 < nc) {
                rec_load(sb + ((c + 2) % 3) * RC_STAGE, hhi, hlo, Whi, Wlo,
                         bn0, kbeg + (c + 2) * 32, tid);
                CP_COMMIT();
            }
            const uint32_t st = sb + (c % 3) * RC_STAGE;

#pragma unroll
            for (int kk = 0; kk < 2; kk++) {
                const uint32_t ko = kk * 32;
                uint32_t ah[2][4], al[2][4], bh[2][4], bl[2][4];
                ldsm4(ah[0], st + aoff + ko);
                ldsm4(ah[1], st + aoff + 1280 + ko);
                ldsm4(al[0], st + 5120 + aoff + ko);
                ldsm4(al[1], st + 5120 + aoff + 1280 + ko);
                ldsm4(bh[0], st + boff + ko);
                ldsm4(bh[1], st + boff + 1280 + ko);
                ldsm4(bl[0], st + 10240 + boff + ko);
                ldsm4(bl[1], st + 10240 + boff + 1280 + ko);
                // pass 1: hi*hi (8 independent accs)
#pragma unroll
                for (int mt = 0; mt < 2; mt++)
#pragma unroll
                    for (int g = 0; g < 2; g++) {
                        mma_bf16(acc[mt][2 * g],     ah[mt], bh[g][0], bh[g][1]);
                        mma_bf16(acc[mt][2 * g + 1], ah[mt], bh[g][2], bh[g][3]);
                    }
                // pass 2: hi*lo
#pragma unroll
                for (int mt = 0; mt < 2; mt++)
#pragma unroll
                    for (int g = 0; g < 2; g++) {
                        mma_bf16(acc[mt][2 * g],     ah[mt], bl[g][0], bl[g][1]);
                        mma_bf16(acc[mt][2 * g + 1], ah[mt], bl[g][2], bl[g][3]);
                    }
                // pass 3: lo*hi
#pragma unroll
                for (int mt = 0; mt < 2; mt++)
#pragma unroll
                    for (int g = 0; g < 2; g++) {
                        mma_bf16(acc[mt][2 * g],     al[mt], bh[g][0], bh[g][1]);
                        mma_bf16(acc[mt][2 * g + 1], al[mt], bh[g][2], bh[g][3]);
                    }
            }
            __syncthreads();
        }

        // Epilogue: write 64x128 partial tile
        {
            const int lr = lid >> 2;
            const int lc = (lid & 3) * 2;
#pragma unroll
            for (int mt = 0; mt < 2; mt++) {
                const int row = (wid & 1) * 32 + mt * 16 + lr;
#pragma unroll
                for (int j = 0; j < 4; j++) {
                    const int col = bn0 + (wid >> 1) * 32 + j * 8 + lc;
                    float* c = acc[mt][j];
                    Pout[(size_t)row * IN3H + col]           = c[0];
                    Pout[(size_t)row * IN3H + col + 1]       = c[1];
                    Pout[(size_t)(row + 8) * IN3H + col]     = c[2];
                    Pout[(size_t)(row + 8) * IN3H + col + 1] = c[3];
                }
            }
        }

        grid_sync(phase);

        // Gate phase
        for (int i = bid * REC_THREADS + tid; i < 2 * BB * HH;
             i += REC_BLOCKS * REC_THREADS) {
            const int d2  = i >> 16;
            const int rem2 = i & 0xFFFF;
            const int b   = rem2 >> 10;
            const int j   = rem2 & 1023;
            const int t   = d2 ? (TT - 1 - s) : s;

            const float* gxp = g_gx + (size_t)d2 * GXSZ + ((size_t)t * BB + b) * IN3H;
            const float* P0 = g_ghp[0][d2] + (size_t)b * IN3H;
            const float* P1 = g_ghp[1][d2] + (size_t)b * IN3H;
            const float* P2 = g_ghp[2][d2] + (size_t)b * IN3H;
            const float* bias2 = bhh_layer + d2 * IN3H;

            float ghr = P0[j]          + P1[j]          + P2[j]          + bias2[j];
            float ghz = P0[HH + j]     + P1[HH + j]     + P2[HH + j]     + bias2[HH + j];
            float ghn = P0[2 * HH + j] + P1[2 * HH + j] + P2[2 * HH + j] + bias2[2 * HH + j];

            float r = 1.f / (1.f + expf(-(gxp[j]      + ghr)));
            float z = 1.f / (1.f + expf(-(gxp[HH + j] + ghz)));
            float n = tanhf(gxp[2 * HH + j] + r * ghn);

            float hold = g_h[i];
            float hnew = n + z * (hold - n);
            g_h[i] = hnew;

            __nv_bfloat16 hi = __float2bfloat16(hnew);
            __nv_bfloat16 lo = __float2bfloat16(hnew - __bfloat162float(hi));
            g_hhi[i] = hi;
            g_hlo[i] = lo;

            size_t oidx = ((size_t)t * BB + b) * INK + (size_t)d2 * HH + j;
            g_ahi[oidx] = hi;
            g_alo[oidx] = lo;

            if (s == TT - 1) hn_out[i] = hnew;
        }

        grid_sync(phase);
    }
}

// ---------------------------------------------------------------------------
// Launch
// ---------------------------------------------------------------------------
extern "C" void kernel_launch(void* const* d_in, const int* in_sizes, int n_in,
                              void* d_out, int out_size) {
    const float* x   = (const float*)d_in[0];  // [T, B, 2048]
    const float* h0  = (const float*)d_in[1];  // [6, B, H]
    const float* wih = (const float*)d_in[2];  // [3, 2, 3072, 2048]
    const float* whh = (const float*)d_in[3];  // [3, 2, 3072, 1024]
    const float* bih = (const float*)d_in[4];  // [3, 2, 3072]
    const float* bhh = (const float*)d_in[5];  // [3, 2, 3072]
    float* out = (float*)d_out;                // [6, B, H]

    __nv_bfloat16 *ahi, *alo, *whi, *wlo, *uhi, *ulo;
    cudaGetSymbolAddress((void**)&ahi, g_ahi);
    cudaGetSymbolAddress((void**)&alo, g_alo);
    cudaGetSymbolAddress((void**)&whi, g_whi);
    cudaGetSymbolAddress((void**)&wlo, g_wlo);
    cudaGetSymbolAddress((void**)&uhi, g_uhi);
    cudaGetSymbolAddress((void**)&ulo, g_ulo);

    cudaFuncSetAttribute(gx_mma_kernel,
                         cudaFuncAttributeMaxDynamicSharedMemorySize, GX_SMEM);
    cudaFuncSetAttribute(gru_recurrent_kernel,
                         cudaFuncAttributeMaxDynamicSharedMemorySize, RC_SMEM);

    {   // split w_ih
        size_t n4 = (size_t)6 * IN3H * INK / 4;
        split_bf16_kernel<<<(unsigned)((n4 + 255) / 256), 256>>>(wih, whi, wlo, n4);
    }
    {   // split w_hh
        size_t n4 = (size_t)6 * IN3H * HH / 4;
        split_bf16_kernel<<<(unsigned)((n4 + 255) / 256), 256>>>(whh, uhi, ulo, n4);
    }
    {   // split x (layer-0 input)
        size_t n4 = (size_t)GX_M * INK / 4;
        split_bf16_kernel<<<(unsigned)((n4 + 255) / 256), 256>>>(x, ahi, alo, n4);
    }

    for (int l = 0; l < 3; l++) {
        gx_mma_kernel<<<dim3(IN3H / 128, GX_M / 128, 2), 256, GX_SMEM>>>(
            whi + (size_t)l * 2 * IN3H * INK,
            wlo + (size_t)l * 2 * IN3H * INK,
            bih + (size_t)l * 2 * IN3H);

        gru_recurrent_kernel<<<REC_BLOCKS, REC_THREADS, RC_SMEM>>>(
            h0  + (size_t)l * 2 * BB * HH,
            uhi + (size_t)l * 2 * IN3H * HH,
            ulo + (size_t)l * 2 * IN3H * HH,
            bhh + (size_t)l * 2 * IN3H,
            out + (size_t)l * 2 * BB * HH);
    }
}

// round 6
// speedup vs baseline: 3.6343x; 1.2021x over previous
#include <cuda_runtime.h>
#include <cuda_bf16.h>
#include <math.h>
#include <stdint.h>
#include <stddef.h>

// Problem constants
#define TT 256
#define BB 64
#define HH 1024
#define IN3H 3072          // 3*H
#define INK 2048           // input width of every layer (IN = 2H)
#define GX_M (TT * BB)     // 16384
#define GXSZ ((size_t)GX_M * IN3H)

#define REC_BLOCKS 144     // 2 dirs * 24 N-tiles(128) * 3 K-splits
#define REC_THREADS 256

// ---------------------------------------------------------------------------
// Scratch (device globals -- no allocation allowed)
// ---------------------------------------------------------------------------
__device__ float g_gx[2 * GXSZ];                        // input gates (fp32)
__device__ float g_ghp[3][2][(size_t)BB * IN3H];        // hidden-gate partials
__device__ float g_h [2 * BB * HH];                     // hidden state fp32
__device__ __nv_bfloat16 g_hhi[2 * BB * HH];            // hidden state hi/lo
__device__ __nv_bfloat16 g_hlo[2 * BB * HH];
__device__ __nv_bfloat16 g_ahi[(size_t)GX_M * INK];     // layer input hi/lo
__device__ __nv_bfloat16 g_alo[(size_t)GX_M * INK];
__device__ __nv_bfloat16 g_whi[(size_t)6 * IN3H * INK]; // w_ih hi/lo
__device__ __nv_bfloat16 g_wlo[(size_t)6 * IN3H * INK];
__device__ __nv_bfloat16 g_uhi[(size_t)6 * IN3H * HH];  // w_hh hi/lo
__device__ __nv_bfloat16 g_ulo[(size_t)6 * IN3H * HH];

__device__ unsigned g_bar_count = 0;
__device__ unsigned g_bar_phase = 0;

// ---------------------------------------------------------------------------
// Baseline-PTX helpers (valid on compute_103)
// ---------------------------------------------------------------------------
__device__ __forceinline__ uint32_t smem_u32(const void* p) {
    uint32_t a;
    asm("{ .reg .u64 t; cvta.to.shared.u64 t, %1; cvt.u32.u64 %0, t; }"
        : "=r"(a) : "l"(p));
    return a;
}

__device__ __forceinline__ void cp_async16(uint32_t dst, const void* src) {
    asm volatile("cp.async.cg.shared.global [%0], [%1], 16;"
                 :: "r"(dst), "l"(src) : "memory");
}
#define CP_COMMIT() asm volatile("cp.async.commit_group;" ::: "memory")
#define CP_WAIT0()  asm volatile("cp.async.wait_group 0;" ::: "memory")
#define CP_WAIT1()  asm volatile("cp.async.wait_group 1;" ::: "memory")

__device__ __forceinline__ void ldsm4(uint32_t* r, uint32_t addr) {
    asm volatile("ldmatrix.sync.aligned.m8n8.x4.shared.b16 {%0,%1,%2,%3}, [%4];"
                 : "=r"(r[0]), "=r"(r[1]), "=r"(r[2]), "=r"(r[3]) : "r"(addr));
}

__device__ __forceinline__ void mma_bf16(float* c, const uint32_t* a,
                                         uint32_t b0, uint32_t b1) {
    asm("mma.sync.aligned.m16n8k16.row.col.f32.bf16.bf16.f32 "
        "{%0,%1,%2,%3}, {%4,%5,%6,%7}, {%8,%9}, {%0,%1,%2,%3};"
        : "+f"(c[0]), "+f"(c[1]), "+f"(c[2]), "+f"(c[3])
        : "r"(a[0]), "r"(a[1]), "r"(a[2]), "r"(a[3]), "r"(b0), "r"(b1));
}

// ---------------------------------------------------------------------------
// Split fp32 -> (bf16 hi, bf16 lo)
// ---------------------------------------------------------------------------
__device__ __forceinline__ uint32_t pack2bf(float a, float b) {
    __nv_bfloat162 t = __floats2bfloat162_rn(a, b);
    return *(uint32_t*)&t;
}

__global__ __launch_bounds__(256) void split_bf16_kernel(
    const float* __restrict__ src, __nv_bfloat16* __restrict__ hi,
    __nv_bfloat16* __restrict__ lo, size_t n4) {
    size_t i = (size_t)blockIdx.x * 256 + threadIdx.x;
    if (i >= n4) return;
    float4 v = ((const float4*)src)[i];
    float h0 = __bfloat162float(__float2bfloat16(v.x));
    float h1 = __bfloat162float(__float2bfloat16(v.y));
    float h2 = __bfloat162float(__float2bfloat16(v.z));
    float h3 = __bfloat162float(__float2bfloat16(v.w));
    uint2 hv, lv;
    hv.x = pack2bf(v.x, v.y);           hv.y = pack2bf(v.z, v.w);
    lv.x = pack2bf(v.x - h0, v.y - h1); lv.y = pack2bf(v.z - h2, v.w - h3);
    ((uint2*)hi)[i] = hv;
    ((uint2*)lo)[i] = lv;
}

// ---------------------------------------------------------------------------
// gx GEMM: 128x128 tile, k-chunk 32, 2-stage cp.async pipeline, 2 CTAs/SM.
// smem stage: Ahi@0, Alo@10240, Bhi@20480, Blo@30720 (rows of 80B).
// ---------------------------------------------------------------------------
#define GX_STAGE 40960
#define GX_SMEM  (2 * GX_STAGE)
#define GX_NCHUNK 64

__device__ __forceinline__ void gx_load(uint32_t sm, int bm, int bn, int k0,
                                        int tid, const __nv_bfloat16* Bhi,
                                        const __nv_bfloat16* Blo) {
#pragma unroll
    for (int half = 0; half < 2; half++) {
        int idx = half * 256 + tid;      // 0..511
        int r   = idx >> 2;
        int co  = k0 + (idx & 3) * 8;
        uint32_t dst = sm + r * 80 + (idx & 3) * 16;
        cp_async16(dst,          g_ahi + (size_t)(bm + r) * INK + co);
        cp_async16(dst + 10240,  g_alo + (size_t)(bm + r) * INK + co);
        cp_async16(dst + 20480,  Bhi   + (size_t)(bn + r) * INK + co);
        cp_async16(dst + 30720,  Blo   + (size_t)(bn + r) * INK + co);
    }
}

__global__ __launch_bounds__(256, 2) void gx_mma_kernel(
    const __nv_bfloat16* __restrict__ Whi,   // [2][3072][2048] (this layer)
    const __nv_bfloat16* __restrict__ Wlo,
    const float* __restrict__ bias)          // [2][3072]
{
    extern __shared__ char smem[];
    const uint32_t sb = smem_u32(smem);
    const int tid = threadIdx.x, wid = tid >> 5, lid = tid & 31;
    const int bn = blockIdx.x * 128;
    const int bm = blockIdx.y * 128;
    const int d  = blockIdx.z;

    const __nv_bfloat16* Bhi = Whi + (size_t)d * IN3H * INK;
    const __nv_bfloat16* Blo = Wlo + (size_t)d * IN3H * INK;
    const float* bptr = bias + d * IN3H;
    float* C = g_gx + (size_t)d * GXSZ;

    const uint32_t aoff = (uint32_t)(((wid & 3) * 32 + (lid & 7) + ((lid >> 3) & 1) * 8) * 80
                                     + ((lid >> 4) & 1) * 16);
    const uint32_t boff = (uint32_t)(((wid >> 2) * 64 + (lid & 7) + ((lid >> 4) & 1) * 8) * 80
                                     + ((lid >> 3) & 1) * 16);

    float acc[2][8][4];
#pragma unroll
    for (int i = 0; i < 2; i++)
#pragma unroll
        for (int j = 0; j < 8; j++)
#pragma unroll
            for (int q = 0; q < 4; q++) acc[i][j][q] = 0.f;

    gx_load(sb, bm, bn, 0, tid, Bhi, Blo); CP_COMMIT();

    for (int c = 0; c < GX_NCHUNK; c++) {
        if (c + 1 < GX_NCHUNK) {
            gx_load(sb + ((c + 1) & 1) * GX_STAGE, bm, bn, (c + 1) * 32, tid, Bhi, Blo);
            CP_COMMIT();
            CP_WAIT1();
        } else {
            CP_WAIT0();
        }
        __syncthreads();
        const uint32_t st = sb + (c & 1) * GX_STAGE;

#pragma unroll
        for (int kk = 0; kk < 2; kk++) {
            const uint32_t ko = kk * 32;
            uint32_t ah[2][4], al[2][4];
            ldsm4(ah[0], st + aoff + ko);
            ldsm4(ah[1], st + aoff + 1280 + ko);
            ldsm4(al[0], st + 10240 + aoff + ko);
            ldsm4(al[1], st + 10240 + aoff + 1280 + ko);
#pragma unroll
            for (int g = 0; g < 4; g++) {
                uint32_t bh[4], bl[4];
                ldsm4(bh, st + 20480 + boff + g * 1280 + ko);
                ldsm4(bl, st + 30720 + boff + g * 1280 + ko);
                mma_bf16(acc[0][2 * g],     ah[0], bh[0], bh[1]);
                mma_bf16(acc[0][2 * g + 1], ah[0], bh[2], bh[3]);
                mma_bf16(acc[1][2 * g],     ah[1], bh[0], bh[1]);
                mma_bf16(acc[1][2 * g + 1], ah[1], bh[2], bh[3]);
                mma_bf16(acc[0][2 * g],     ah[0], bl[0], bl[1]);
                mma_bf16(acc[0][2 * g + 1], ah[0], bl[2], bl[3]);
                mma_bf16(acc[1][2 * g],     ah[1], bl[0], bl[1]);
                mma_bf16(acc[1][2 * g + 1], ah[1], bl[2], bl[3]);
                mma_bf16(acc[0][2 * g],     al[0], bh[0], bh[1]);
                mma_bf16(acc[0][2 * g + 1], al[0], bh[2], bh[3]);
                mma_bf16(acc[1][2 * g],     al[1], bh[0], bh[1]);
                mma_bf16(acc[1][2 * g + 1], al[1], bh[2], bh[3]);
            }
        }
        __syncthreads();
    }

    // Epilogue: D + bias -> fp32 gx
    const int lr = lid >> 2;
    const int lc = (lid & 3) * 2;
#pragma unroll
    for (int mt = 0; mt < 2; mt++) {
        const int row = bm + (wid & 3) * 32 + mt * 16 + lr;
#pragma unroll
        for (int nt = 0; nt < 8; nt++) {
            const int col = bn + (wid >> 2) * 64 + nt * 8 + lc;
            float b0 = bptr[col], b1 = bptr[col + 1];
            float* c = acc[mt][nt];
            C[(size_t)row * IN3H + col]           = c[0] + b0;
            C[(size_t)row * IN3H + col + 1]       = c[1] + b1;
            C[(size_t)(row + 8) * IN3H + col]     = c[2] + b0;
            C[(size_t)(row + 8) * IN3H + col + 1] = c[3] + b1;
        }
    }
}

// ---------------------------------------------------------------------------
// Grid-wide barrier (spin, monotonic phase)
// ---------------------------------------------------------------------------
__device__ __forceinline__ void grid_sync(unsigned& local_phase) {
    __threadfence();
    __syncthreads();
    if (threadIdx.x == 0) {
        unsigned ph = local_phase;
        if (atomicAdd(&g_bar_count, 1u) == REC_BLOCKS - 1) {
            g_bar_count = 0;
            __threadfence();
            atomicAdd(&g_bar_phase, 1u);
        } else {
            while (*(volatile unsigned*)&g_bar_phase == ph) { }
        }
        __threadfence();
    }
    __syncthreads();
    local_phase++;
}

// ---------------------------------------------------------------------------
// Persistent recurrent kernel with SMEM-RESIDENT WEIGHTS.
// 144 blocks = 2 dirs x 24 N-tiles(128) x 3 K-splits ({352,352,320}).
// Each block holds its Whh hi/lo tile in smem for all 256 steps; per step it
// streams only the h chunks (2-stage cp.async) and computes a 64x128 partial.
//
// smem map (dynamic, 200704 B):
//   A stages: [2][ hi 5120 | lo 5120 ]                  @ 0      (20480)
//   B hi:     [chunk][128 rows][64 B, segs XOR-swizzled] @ 20480  (90112)
//   B lo:                                               @ 110592 (90112)
// Swizzle: seg' = seg ^ ((row>>1)&3) -> conflict-free LDSM with 64B rows.
// ---------------------------------------------------------------------------
#define RC_SB_BHI 20480
#define RC_SB_BLO 110592
#define RC_SMEM   200704

__global__ __launch_bounds__(REC_THREADS)
void gru_recurrent_kernel(const float* __restrict__ h0_layer,    // [2,B,H]
                          const __nv_bfloat16* __restrict__ Uhi, // [2,3H,H]
                          const __nv_bfloat16* __restrict__ Ulo,
                          const float* __restrict__ bhh_layer,   // [2,3H]
                          float* __restrict__ hn_out)            // [2,B,H]
{
    extern __shared__ char smem[];
    const uint32_t sb = smem_u32(smem);
    const int bid = blockIdx.x, tid = threadIdx.x;
    const int wid = tid >> 5, lid = tid & 31;
    const int d   = bid / 72;
    const int rem = bid % 72;
    const int nt  = rem / 3;            // 0..23 -> 128 gh columns each
    const int ks  = rem % 3;            // K split
    const int bn0  = nt * 128;
    const int kbeg = ks * 352;          // {0, 352, 704}
    const int nc   = (ks == 2) ? 10 : 11;   // chunks of 32 k

    const __nv_bfloat16* Whi = Uhi + (size_t)d * IN3H * HH;
    const __nv_bfloat16* Wlo = Ulo + (size_t)d * IN3H * HH;
    float* Pout = g_ghp[ks][d];

    unsigned phase = *(volatile unsigned*)&g_bar_phase;
    __syncthreads();

    // ---- One-time weight preload into resident smem (swizzled) ----
    for (int idx = tid; idx < nc * 512; idx += REC_THREADS) {
        int chunk = idx >> 9;
        int r     = (idx >> 2) & 127;
        int seg   = idx & 3;
        int col   = kbeg + chunk * 32 + seg * 8;
        uint32_t dst = (uint32_t)(chunk * 8192 + r * 64
                                  + ((seg ^ ((r >> 1) & 3)) * 16));
        cp_async16(sb + RC_SB_BHI + dst, Whi + (size_t)(bn0 + r) * HH + col);
        cp_async16(sb + RC_SB_BLO + dst, Wlo + (size_t)(bn0 + r) * HH + col);
    }
    CP_COMMIT();
    CP_WAIT0();

    // Prologue: split h0 into fp32 + bf16 hi/lo state
    for (int i = bid * REC_THREADS + tid; i < 2 * BB * HH;
         i += REC_BLOCKS * REC_THREADS) {
        float v = h0_layer[i];
        g_h[i] = v;
        __nv_bfloat16 hi = __float2bfloat16(v);
        g_hhi[i] = hi;
        g_hlo[i] = __float2bfloat16(v - __bfloat162float(hi));
    }
    grid_sync(phase);

    // A ldmatrix offsets (80B padded rows): warp m = (wid&1)*32
    const uint32_t aoff = (uint32_t)(((wid & 1) * 32 + (lid & 7) + ((lid >> 3) & 1) * 8) * 80
                                     + ((lid >> 4) & 1) * 16);
    // B ldmatrix components (64B rows, XOR swizzle). Key is g-invariant.
    const int brow0 = (wid >> 1) * 32 + (lid & 7) + ((lid >> 4) & 1) * 8;
    const int bkey  = (brow0 >> 1) & 3;
    const int lb3   = (lid >> 3) & 1;
    const uint32_t bseg0 = (uint32_t)(((0 + lb3) ^ bkey) * 16);  // kk=0
    const uint32_t bseg1 = (uint32_t)(((2 + lb3) ^ bkey) * 16);  // kk=1
    const uint32_t bbase = (uint32_t)(brow0 * 64);

    const __nv_bfloat16* hhi = g_hhi + (size_t)d * BB * HH;
    const __nv_bfloat16* hlo = g_hlo + (size_t)d * BB * HH;

    // A chunk loader: 64 rows x 32 k (hi+lo), 256 threads = 1 iteration
    const int a_r  = tid >> 2;
    const int a_sg = tid & 3;

    for (int s = 0; s < TT; s++) {
        float acc[2][4][4];
#pragma unroll
        for (int i = 0; i < 2; i++)
#pragma unroll
            for (int j = 0; j < 4; j++)
#pragma unroll
                for (int q = 0; q < 4; q++) acc[i][j][q] = 0.f;

        {   // prologue A load, chunk 0
            uint32_t dst = sb + a_r * 80 + a_sg * 16;
            const int co = kbeg + a_sg * 8;
            cp_async16(dst,        hhi + (size_t)a_r * HH + co);
            cp_async16(dst + 5120, hlo + (size_t)a_r * HH + co);
            CP_COMMIT();
        }

        for (int c = 0; c < nc; c++) {
            if (c + 1 < nc) {
                uint32_t dst = sb + ((c + 1) & 1) * 10240 + a_r * 80 + a_sg * 16;
                const int co = kbeg + (c + 1) * 32 + a_sg * 8;
                cp_async16(dst,        hhi + (size_t)a_r * HH + co);
                cp_async16(dst + 5120, hlo + (size_t)a_r * HH + co);
                CP_COMMIT();
                CP_WAIT1();
            } else {
                CP_WAIT0();
            }
            __syncthreads();
            const uint32_t stA = sb + (c & 1) * 10240;
            const uint32_t stBh = sb + RC_SB_BHI + c * 8192 + bbase;
            const uint32_t stBl = sb + RC_SB_BLO + c * 8192 + bbase;

#pragma unroll
            for (int kk = 0; kk < 2; kk++) {
                const uint32_t ko  = kk * 32;                  // A byte offset
                const uint32_t bso = kk ? bseg1 : bseg0;       // B swizzled seg
                uint32_t ah[2][4], al[2][4], bh[2][4], bl[2][4];
                ldsm4(ah[0], stA + aoff + ko);
                ldsm4(ah[1], stA + aoff + 1280 + ko);
                ldsm4(al[0], stA + 5120 + aoff + ko);
                ldsm4(al[1], stA + 5120 + aoff + 1280 + ko);
                ldsm4(bh[0], stBh + bso);
                ldsm4(bh[1], stBh + 1024 + bso);   // +16 rows * 64B
                ldsm4(bl[0], stBl + bso);
                ldsm4(bl[1], stBl + 1024 + bso);
                // pass 1: hi*hi (8 independent accs)
#pragma unroll
                for (int mt = 0; mt < 2; mt++)
#pragma unroll
                    for (int g = 0; g < 2; g++) {
                        mma_bf16(acc[mt][2 * g],     ah[mt], bh[g][0], bh[g][1]);
                        mma_bf16(acc[mt][2 * g + 1], ah[mt], bh[g][2], bh[g][3]);
                    }
                // pass 2: hi*lo
#pragma unroll
                for (int mt = 0; mt < 2; mt++)
#pragma unroll
                    for (int g = 0; g < 2; g++) {
                        mma_bf16(acc[mt][2 * g],     ah[mt], bl[g][0], bl[g][1]);
                        mma_bf16(acc[mt][2 * g + 1], ah[mt], bl[g][2], bl[g][3]);
                    }
                // pass 3: lo*hi
#pragma unroll
                for (int mt = 0; mt < 2; mt++)
#pragma unroll
                    for (int g = 0; g < 2; g++) {
                        mma_bf16(acc[mt][2 * g],     al[mt], bh[g][0], bh[g][1]);
                        mma_bf16(acc[mt][2 * g + 1], al[mt], bh[g][2], bh[g][3]);
                    }
            }
            __syncthreads();
        }

        // Epilogue: write 64x128 partial tile
        {
            const int lr = lid >> 2;
            const int lc = (lid & 3) * 2;
#pragma unroll
            for (int mt = 0; mt < 2; mt++) {
                const int row = (wid & 1) * 32 + mt * 16 + lr;
#pragma unroll
                for (int j = 0; j < 4; j++) {
                    const int col = bn0 + (wid >> 1) * 32 + j * 8 + lc;
                    float* c = acc[mt][j];
                    Pout[(size_t)row * IN3H + col]           = c[0];
                    Pout[(size_t)row * IN3H + col + 1]       = c[1];
                    Pout[(size_t)(row + 8) * IN3H + col]     = c[2];
                    Pout[(size_t)(row + 8) * IN3H + col + 1] = c[3];
                }
            }
        }

        grid_sync(phase);

        // Gate phase
        for (int i = bid * REC_THREADS + tid; i < 2 * BB * HH;
             i += REC_BLOCKS * REC_THREADS) {
            const int d2   = i >> 16;
            const int rem2 = i & 0xFFFF;
            const int b    = rem2 >> 10;
            const int j    = rem2 & 1023;
            const int t    = d2 ? (TT - 1 - s) : s;

            const float* gxp = g_gx + (size_t)d2 * GXSZ + ((size_t)t * BB + b) * IN3H;
            const float* P0 = g_ghp[0][d2] + (size_t)b * IN3H;
            const float* P1 = g_ghp[1][d2] + (size_t)b * IN3H;
            const float* P2 = g_ghp[2][d2] + (size_t)b * IN3H;
            const float* bias2 = bhh_layer + d2 * IN3H;

            float ghr = P0[j]          + P1[j]          + P2[j]          + bias2[j];
            float ghz = P0[HH + j]     + P1[HH + j]     + P2[HH + j]     + bias2[HH + j];
            float ghn = P0[2 * HH + j] + P1[2 * HH + j] + P2[2 * HH + j] + bias2[2 * HH + j];

            float r = 1.f / (1.f + expf(-(gxp[j]      + ghr)));
            float z = 1.f / (1.f + expf(-(gxp[HH + j] + ghz)));
            float n = tanhf(gxp[2 * HH + j] + r * ghn);

            float hold = g_h[i];
            float hnew = n + z * (hold - n);
            g_h[i] = hnew;

            __nv_bfloat16 hi = __float2bfloat16(hnew);
            __nv_bfloat16 lo = __float2bfloat16(hnew - __bfloat162float(hi));
            g_hhi[i] = hi;
            g_hlo[i] = lo;

            size_t oidx = ((size_t)t * BB + b) * INK + (size_t)d2 * HH + j;
            g_ahi[oidx] = hi;
            g_alo[oidx] = lo;

            if (s == TT - 1) hn_out[i] = hnew;
        }

        grid_sync(phase);
    }
}

// ---------------------------------------------------------------------------
// Launch
// ---------------------------------------------------------------------------
extern "C" void kernel_launch(void* const* d_in, const int* in_sizes, int n_in,
                              void* d_out, int out_size) {
    const float* x   = (const float*)d_in[0];  // [T, B, 2048]
    const float* h0  = (const float*)d_in[1];  // [6, B, H]
    const float* wih = (const float*)d_in[2];  // [3, 2, 3072, 2048]
    const float* whh = (const float*)d_in[3];  // [3, 2, 3072, 1024]
    const float* bih = (const float*)d_in[4];  // [3, 2, 3072]
    const float* bhh = (const float*)d_in[5];  // [3, 2, 3072]
    float* out = (float*)d_out;                // [6, B, H]

    __nv_bfloat16 *ahi, *alo, *whi, *wlo, *uhi, *ulo;
    cudaGetSymbolAddress((void**)&ahi, g_ahi);
    cudaGetSymbolAddress((void**)&alo, g_alo);
    cudaGetSymbolAddress((void**)&whi, g_whi);
    cudaGetSymbolAddress((void**)&wlo, g_wlo);
    cudaGetSymbolAddress((void**)&uhi, g_uhi);
    cudaGetSymbolAddress((void**)&ulo, g_ulo);

    cudaFuncSetAttribute(gx_mma_kernel,
                         cudaFuncAttributeMaxDynamicSharedMemorySize, GX_SMEM);
    cudaFuncSetAttribute(gru_recurrent_kernel,
                         cudaFuncAttributeMaxDynamicSharedMemorySize, RC_SMEM);

    {   // split w_ih
        size_t n4 = (size_t)6 * IN3H * INK / 4;
        split_bf16_kernel<<<(unsigned)((n4 + 255) / 256), 256>>>(wih, whi, wlo, n4);
    }
    {   // split w_hh
        size_t n4 = (size_t)6 * IN3H * HH / 4;
        split_bf16_kernel<<<(unsigned)((n4 + 255) / 256), 256>>>(whh, uhi, ulo, n4);
    }
    {   // split x (layer-0 input)
        size_t n4 = (size_t)GX_M * INK / 4;
        split_bf16_kernel<<<(unsigned)((n4 + 255) / 256), 256>>>(x, ahi, alo, n4);
    }

    for (int l = 0; l < 3; l++) {
        gx_mma_kernel<<<dim3(IN3H / 128, GX_M / 128, 2), 256, GX_SMEM>>>(
            whi + (size_t)l * 2 * IN3H * INK,
            wlo + (size_t)l * 2 * IN3H * INK,
            bih + (size_t)l * 2 * IN3H);

        gru_recurrent_kernel<<<REC_BLOCKS, REC_THREADS, RC_SMEM>>>(
            h0  + (size_t)l * 2 * BB * HH,
            uhi + (size_t)l * 2 * IN3H * HH,
            ulo + (size_t)l * 2 * IN3H * HH,
            bhh + (size_t)l * 2 * IN3H,
            out + (size_t)l * 2 * BB * HH);
    }
}